// round 14
// baseline (speedup 1.0000x reference)
#include <cuda_runtime.h>
#include <cuda_bf16.h>
#include <cstdint>
#include <math.h>

#define C256 256

// ---------------------------------------------------------------------------
// Scratch (device globals; no allocations allowed)
// ---------------------------------------------------------------------------
__device__ __nv_bfloat16 g_Wh[4][C256 * C256];
__device__ __nv_bfloat16 g_P1[8 * 1600 * C256];
__device__ __nv_bfloat16 g_P2[8 *  400 * C256];
__device__ __nv_bfloat16 g_P3[8 *  100 * C256];
__device__ float g_part_fine[8 * 50 * 3];
__device__ float g_part_coarse[8 * 5 * 3];
__device__ unsigned int g_wdone;       // converters done (4)
__device__ unsigned int g_small_done;  // small gemms done (144)
__device__ unsigned int g_ticket;      // fine+coarse tickets (440)

__device__ __forceinline__ uint32_t smem_to_u32(const void* p) {
    uint32_t a;
    asm("{ .reg .u64 t; cvta.to.shared.u64 t, %1; cvt.u32.u64 %0, t; }"
        : "=r"(a) : "l"(p));
    return a;
}

#define CP16(dst, src, sz) \
    asm volatile("cp.async.cg.shared.global [%0], [%1], 16, %2;" \
                 :: "r"(dst), "l"(src), "r"(sz))
#define CP_COMMIT() asm volatile("cp.async.commit_group;" ::: "memory")
#define CP_WAIT0()  asm volatile("cp.async.wait_group 0;" ::: "memory")

__device__ __forceinline__ void ldx4(uint32_t* r, uint32_t addr) {
    asm volatile("ldmatrix.sync.aligned.m8n8.x4.shared.b16 {%0,%1,%2,%3}, [%4];"
                 : "=r"(r[0]), "=r"(r[1]), "=r"(r[2]), "=r"(r[3]) : "r"(addr));
}
__device__ __forceinline__ void ldx4t(uint32_t* r, uint32_t addr) {
    asm volatile("ldmatrix.sync.aligned.m8n8.x4.trans.shared.b16 {%0,%1,%2,%3}, [%4];"
                 : "=r"(r[0]), "=r"(r[1]), "=r"(r[2]), "=r"(r[3]) : "r"(addr));
}
__device__ __forceinline__ void mma16816(float* d, const uint32_t* a, const uint32_t* b) {
    asm volatile("mma.sync.aligned.m16n8k16.row.col.f32.bf16.bf16.f32 "
                 "{%0,%1,%2,%3}, {%4,%5,%6,%7}, {%8,%9}, {%0,%1,%2,%3};"
                 : "+f"(d[0]), "+f"(d[1]), "+f"(d[2]), "+f"(d[3])
                 : "r"(a[0]), "r"(a[1]), "r"(a[2]), "r"(a[3]), "r"(b[0]), "r"(b[1]));
}
__device__ __forceinline__ void exp8(uint4 u, float* f) {
    f[0] = __uint_as_float(u.x << 16); f[1] = __uint_as_float(u.x & 0xffff0000u);
    f[2] = __uint_as_float(u.y << 16); f[3] = __uint_as_float(u.y & 0xffff0000u);
    f[4] = __uint_as_float(u.z << 16); f[5] = __uint_as_float(u.z & 0xffff0000u);
    f[6] = __uint_as_float(u.w << 16); f[7] = __uint_as_float(u.w & 0xffff0000u);
}

// release: all block threads wrote -> __syncthreads -> t0 fence + count.
// acquire: t0 spins on counter, fence, __syncthreads broadcasts.
#define SPIN_ON(ctr, target) do {                                             \
        if (threadIdx.x == 0) {                                               \
            while (atomicAdd(&(ctr), 0u) < (target)) { }                      \
            __threadfence();                                                  \
        }                                                                     \
        __syncthreads();                                                      \
    } while (0)

// ---------------------------------------------------------------------------
// GEMM tile config: BM=256, BN=128, BK=32, 512 threads (4x4 warps).
// ---------------------------------------------------------------------------
#define A_ROWB 80u
#define A_TILE (256u * A_ROWB)          // 20480
#define B_ROWB 272u
#define B_TILE (32u * B_ROWB)           // 8704
#define STAGE  (A_TILE + B_TILE)        // 29184
#define EP_ROWB 528u
#define GEMM_SMEM (128u * EP_ROWB)      // 67584 > 2*STAGE

#define GEMM_DECLS()                                                           \
    const uint32_t sb = smem_to_u32(sm);                                       \
    const int tid = threadIdx.x;                                               \
    const int wid = tid >> 5, lane = tid & 31;                                 \
    const int arow = tid >> 1;                                                 \
    const int c2   = (tid & 1) * 2;                                            \
    const uint32_t aOff = arow * A_ROWB + c2 * 16;                             \
    const int cloc = tid >> 4;                                                 \
    const int lcol = (tid & 15) * 8;                                           \
    const int r8 = lane & 7, sel = lane >> 3;                                  \
    const int warp_m = wid >> 2, warp_n = wid & 3;                             \
    const uint32_t aRel = (uint32_t)((warp_m * 64 + r8 + (sel & 1) * 8) * A_ROWB \
                                     + (sel >> 1) * 16);                       \
    const uint32_t bRel = (uint32_t)(A_TILE                                    \
                          + ((sel & 1) * 8 + r8) * B_ROWB                      \
                          + (warp_n * 32 + (sel >> 1) * 8) * 2)

#define ISSUE_A(kc, st) do {                                                  \
        const uint32_t base = sb + (uint32_t)(st) * STAGE;                    \
        const int ko = (kc) * 64;                                             \
        CP16(base + aOff,      srcAh + ko,      16u);                         \
        CP16(base + aOff + 16, srcAh + ko + 16, 16u);                         \
        CP_COMMIT();                                                          \
    } while (0)

#define STS_B(st) do {                                                        \
        char* bp = sm + (size_t)(st) * STAGE + A_TILE                         \
                   + (size_t)cloc * B_ROWB + lcol * 2;                        \
        uint4 p0;                                                             \
        __nv_bfloat162 t;                                                     \
        t = __float22bfloat162_rn(make_float2(v[0].x, v[0].y)); p0.x = *(uint32_t*)&t; \
        t = __float22bfloat162_rn(make_float2(v[0].z, v[0].w)); p0.y = *(uint32_t*)&t; \
        t = __float22bfloat162_rn(make_float2(v[1].x, v[1].y)); p0.z = *(uint32_t*)&t; \
        t = __float22bfloat162_rn(make_float2(v[1].z, v[1].w)); p0.w = *(uint32_t*)&t; \
        *(uint4*)(bp) = p0;                                                   \
    } while (0)

#define GEMM_MAINLOOP(LDG_B_MACRO)                                            \
    float acc[4][4][4];                                                       \
    _Pragma("unroll")                                                         \
    for (int i = 0; i < 4; ++i)                                               \
        _Pragma("unroll")                                                     \
        for (int j = 0; j < 4; ++j)                                           \
            _Pragma("unroll")                                                 \
            for (int k = 0; k < 4; ++k) acc[i][j][k] = 0.f;                   \
    LDG_B_MACRO(0);                                                           \
    STS_B(0);                                                                 \
    ISSUE_A(0, 0);                                                            \
    CP_WAIT0();                                                               \
    __syncthreads();                                                          \
    for (int kc = 0; kc < 8; ++kc) {                                          \
        const int st = kc & 1;                                                \
        if (kc < 7) { LDG_B_MACRO(kc + 1); ISSUE_A(kc + 1, st ^ 1); }         \
        const uint32_t stage = sb + (uint32_t)st * STAGE;                     \
        _Pragma("unroll")                                                     \
        for (int ks = 0; ks < 2; ++ks) {                                      \
            uint32_t bf[8];                                                   \
            ldx4t(bf,     stage + bRel + ks * 16 * B_ROWB);                   \
            ldx4t(bf + 4, stage + bRel + ks * 16 * B_ROWB + 32);              \
            uint32_t af[4];                                                   \
            _Pragma("unroll")                                                 \
            for (int mt = 0; mt < 4; ++mt) {                                  \
                ldx4(af, stage + aRel + ks * 32 + mt * 16 * A_ROWB);          \
                _Pragma("unroll")                                             \
                for (int nt = 0; nt < 4; ++nt)                                \
                    mma16816(acc[mt][nt], af, bf + (nt >> 1) * 4 + (nt & 1) * 2); \
            }                                                                 \
        }                                                                     \
        if (kc < 7) { STS_B(st ^ 1); CP_WAIT0(); }                            \
        __syncthreads();                                                      \
    }

#define GEMM_STAGE_EP()                                                       \
    {                                                                         \
        float bv[4][2];                                                       \
        _Pragma("unroll")                                                     \
        for (int mt = 0; mt < 4; ++mt) {                                      \
            const int m = warp_m * 64 + mt * 16 + (lane >> 2);                \
            bv[mt][0] = bias[m];                                              \
            bv[mt][1] = bias[m + 8];                                          \
        }                                                                     \
        __nv_bfloat16* ep = (__nv_bfloat16*)sm;                               \
        _Pragma("unroll")                                                     \
        for (int mt = 0; mt < 4; ++mt) {                                      \
            const int m = warp_m * 64 + mt * 16 + (lane >> 2);                \
            _Pragma("unroll")                                                 \
            for (int nt = 0; nt < 4; ++nt) {                                  \
                const int n = warp_n * 32 + nt * 8 + (lane & 3) * 2;          \
                ep[(size_t)n       * 264 + m]     = __float2bfloat16(acc[mt][nt][0] + bv[mt][0]); \
                ep[(size_t)(n + 1) * 264 + m]     = __float2bfloat16(acc[mt][nt][1] + bv[mt][0]); \
                ep[(size_t)n       * 264 + m + 8] = __float2bfloat16(acc[mt][nt][2] + bv[mt][1]); \
                ep[(size_t)(n + 1) * 264 + m + 8] = __float2bfloat16(acc[mt][nt][3] + bv[mt][1]); \
            }                                                                 \
        }                                                                     \
        __syncthreads();                                                      \
    }

// ---------------------------------------------------------------------------
// MEGA kernel: 588 blocks.
//   0..3    : W->bf16 converters (one scale each)
//   4..147  : small gemms (scales 1..3) -> P1..P3
//   148..547: scale-0 gemm + fused fine cosine
//   548..587: coarse pair sums
//   last ticket of the 440 fine+coarse blocks: final softmax + counter reset
// ---------------------------------------------------------------------------
__global__ __launch_bounds__(512, 1)
void mega(const float* __restrict__ f0, const float* __restrict__ f1,
          const float* __restrict__ f2, const float* __restrict__ f3,
          const float* __restrict__ w0, const float* __restrict__ w1,
          const float* __restrict__ w2, const float* __restrict__ w3,
          const float* __restrict__ b0, const float* __restrict__ b1,
          const float* __restrict__ b2, const float* __restrict__ b3,
          float* __restrict__ out)
{
    extern __shared__ char sm[];
    __shared__ float sh2[16][3];
    __shared__ unsigned int sh_last;
    const int id = blockIdx.x;

    // ================= converters =================
    if (id < 4) {
        const float* w = (id == 0) ? w0 : (id == 1) ? w1 : (id == 2) ? w2 : w3;
        for (int i = threadIdx.x; i < 16384; i += 512) {
            const float4 v = ((const float4*)w)[i];
            __nv_bfloat162 lo = __float22bfloat162_rn(make_float2(v.x, v.y));
            __nv_bfloat162 hi = __float22bfloat162_rn(make_float2(v.z, v.w));
            uint2 pk;
            pk.x = *(uint32_t*)&lo;
            pk.y = *(uint32_t*)&hi;
            ((uint2*)g_Wh[id])[i] = pk;
        }
        __syncthreads();
        if (threadIdx.x == 0) { __threadfence(); atomicAdd(&g_wdone, 1u); }
        return;
    }

    // ================= small gemms (scales 1..3) =================
    if (id < 148) {
        GEMM_DECLS();
        const int sid = id - 4;
        int s, off, L;
        const float* F;
        const float* bias;
        __nv_bfloat16* P;
        if (sid < 104)      { s = 1; off = 0;   L = 1600; F = f1; bias = b1; P = g_P1; }
        else if (sid < 136) { s = 2; off = 104; L = 400;  F = f2; bias = b2; P = g_P2; }
        else                { s = 3; off = 136; L = 100;  F = f3; bias = b3; P = g_P3; }
        const int local = sid - off;
        const int l0    = (local >> 3) * 128;
        const int batch = local & 7;

        const float* Fb = F + (size_t)batch * C256 * L;
        __nv_bfloat16* Pb = P + (size_t)batch * L * C256;
        const char* srcAh = (const char*)(g_Wh[s] + (size_t)arow * C256) + c2 * 16;

        SPIN_ON(g_wdone, 4u);

        float4 v[2];
#define LDG_BS(kc) do {                                                       \
        const int ch = (kc) * 32 + cloc;                                      \
        const float* rp = Fb + (size_t)ch * L + l0 + lcol;                    \
        _Pragma("unroll")                                                     \
        for (int i = 0; i < 2; ++i)                                           \
            v[i] = (l0 + lcol + i * 4 < L) ? *(const float4*)(rp + i * 4)     \
                                           : make_float4(0.f, 0.f, 0.f, 0.f); \
    } while (0)

        GEMM_MAINLOOP(LDG_BS);
        GEMM_STAGE_EP();

        const int n = tid >> 2, quarter = tid & 3;
        if (l0 + n < L) {
            const uint4* src = (const uint4*)((const char*)sm + (size_t)n * EP_ROWB + quarter * 128);
            uint4* dst = (uint4*)(Pb + (size_t)(l0 + n) * C256 + quarter * 64);
#pragma unroll
            for (int i = 0; i < 8; ++i) dst[i] = src[i];
        }
        __syncthreads();
        if (tid == 0) { __threadfence(); atomicAdd(&g_small_done, 1u); }
        return;
#undef LDG_BS
    }

    // ================= scale-0 gemm + fused fine cosine =================
    if (id < 548) {
        GEMM_DECLS();
        const int fid   = id - 148;          // 0..399
        const int l0    = (fid >> 3) * 128;
        const int batch = fid & 7;
        const float* Fb = f0 + (size_t)batch * C256 * 6400;
        const float* bias = b0;
        const char* srcAh = (const char*)(g_Wh[0] + (size_t)arow * C256) + c2 * 16;

        SPIN_ON(g_wdone, 4u);

        float4 v[2];
#define LDG_B0(kc) do {                                                       \
        const int ch = (kc) * 32 + cloc;                                      \
        const float* rp = Fb + (size_t)ch * 6400 + l0 + lcol;                 \
        v[0] = *(const float4*)(rp);                                          \
        v[1] = *(const float4*)(rp + 4);                                      \
    } while (0)

        GEMM_MAINLOOP(LDG_B0);
        GEMM_STAGE_EP();

        // P1..P3 must be final before the cosine reads them
        SPIN_ON(g_small_done, 144u);

        float a01 = 0.f, a02 = 0.f, a03 = 0.f;
        for (int i = 0; i < 8; ++i) {
            const int n = wid * 8 + i;
            const int l = l0 + n;
            const int h = l / 80;
            const int wim = l - h * 80;
            const uint4 u0 = *(const uint4*)(sm + (size_t)n * EP_ROWB + lane * 16);
            const uint4 u1 = ((const uint4*)(g_P1 + (size_t)(batch * 1600 + (h >> 1) * 40 + (wim >> 1)) * C256))[lane];
            const uint4 u2 = ((const uint4*)(g_P2 + (size_t)(batch *  400 + (h >> 2) * 20 + (wim >> 2)) * C256))[lane];
            const uint4 u3 = ((const uint4*)(g_P3 + (size_t)(batch *  100 + (h >> 3) * 10 + (wim >> 3)) * C256))[lane];
            float e0[8], e1[8], e2[8], e3[8];
            exp8(u0, e0); exp8(u1, e1); exp8(u2, e2); exp8(u3, e3);
            float d[7];
#pragma unroll
            for (int k = 0; k < 7; ++k) d[k] = 0.f;
#pragma unroll
            for (int e = 0; e < 8; ++e) {
                d[0] += e0[e] * e0[e];
                d[1] += e1[e] * e1[e];
                d[2] += e2[e] * e2[e];
                d[3] += e3[e] * e3[e];
                d[4] += e0[e] * e1[e];
                d[5] += e0[e] * e2[e];
                d[6] += e0[e] * e3[e];
            }
#pragma unroll
            for (int off = 16; off > 0; off >>= 1) {
#pragma unroll
                for (int k = 0; k < 7; ++k)
                    d[k] += __shfl_xor_sync(0xFFFFFFFFu, d[k], off);
            }
            if (lane == 0) {
                const float n0 = sqrtf(d[0]);
                const float n1 = sqrtf(d[1]);
                const float n2 = sqrtf(d[2]);
                const float n3 = sqrtf(d[3]);
                a01 += d[4] / fmaxf(n0 * n1, 1e-8f);
                a02 += d[5] / fmaxf(n0 * n2, 1e-8f);
                a03 += d[6] / fmaxf(n0 * n3, 1e-8f);
            }
        }
        if (lane == 0) { sh2[wid][0] = a01; sh2[wid][1] = a02; sh2[wid][2] = a03; }
        __syncthreads();
        if (tid == 0) {
            float* dst = &g_part_fine[((size_t)batch * 50 + (fid >> 3)) * 3];
#pragma unroll
            for (int k = 0; k < 3; ++k) {
                float ss = 0.f;
#pragma unroll
                for (int i = 0; i < 16; ++i) ss += sh2[i][k];
                dst[k] = ss;
            }
        }
#undef LDG_B0
    } else {
        // ================= coarse pairs =================
        const int tid = threadIdx.x;
        const int wid = tid >> 5, lane = tid & 31;
        const int c = id - 548;             // 0..39
        const int batch = c / 5;
        const int seg   = c - batch * 5;    // 0..4

        SPIN_ON(g_small_done, 144u);

        float a12 = 0.f, a13 = 0.f, a23 = 0.f;
        for (int i = 0; i < 20; ++i) {
            const int loc = seg * 320 + wid * 20 + i;
            const int h1 = loc / 40;
            const int w1 = loc - h1 * 40;
            const uint4 u1 = ((const uint4*)(g_P1 + (size_t)(batch * 1600 + loc) * C256))[lane];
            const uint4 u2 = ((const uint4*)(g_P2 + (size_t)(batch *  400 + (h1 >> 1) * 20 + (w1 >> 1)) * C256))[lane];
            const uint4 u3 = ((const uint4*)(g_P3 + (size_t)(batch *  100 + (h1 >> 2) * 10 + (w1 >> 2)) * C256))[lane];
            float e1[8], e2[8], e3[8];
            exp8(u1, e1); exp8(u2, e2); exp8(u3, e3);
            float d[6];
#pragma unroll
            for (int k = 0; k < 6; ++k) d[k] = 0.f;
#pragma unroll
            for (int e = 0; e < 8; ++e) {
                d[0] += e1[e] * e1[e];
                d[1] += e2[e] * e2[e];
                d[2] += e3[e] * e3[e];
                d[3] += e1[e] * e2[e];
                d[4] += e1[e] * e3[e];
                d[5] += e2[e] * e3[e];
            }
#pragma unroll
            for (int off = 16; off > 0; off >>= 1) {
#pragma unroll
                for (int k = 0; k < 6; ++k)
                    d[k] += __shfl_xor_sync(0xFFFFFFFFu, d[k], off);
            }
            if (lane == 0) {
                const float n1 = sqrtf(d[0]);
                const float n2 = sqrtf(d[1]);
                const float n3 = sqrtf(d[2]);
                a12 += d[3] / fmaxf(n1 * n2, 1e-8f);
                a13 += d[4] / fmaxf(n1 * n3, 1e-8f);
                a23 += d[5] / fmaxf(n2 * n3, 1e-8f);
            }
        }
        if (lane == 0) { sh2[wid][0] = a12 * 4.f; sh2[wid][1] = a13 * 4.f; sh2[wid][2] = a23 * 4.f; }
        __syncthreads();
        if (tid == 0) {
            float* dst = &g_part_coarse[((size_t)batch * 5 + seg) * 3];
#pragma unroll
            for (int k = 0; k < 3; ++k) {
                float ss = 0.f;
#pragma unroll
                for (int i = 0; i < 16; ++i) ss += sh2[i][k];
                dst[k] = ss;
            }
        }
    }

    // ================= ticket + final softmax =================
    __syncthreads();
    if (threadIdx.x == 0) {
        __threadfence();
        sh_last = (atomicAdd(&g_ticket, 1u) == 439u);
    }
    __syncthreads();
    if (sh_last) {
        __threadfence();
        const int t = threadIdx.x;
        if (t < 8) {
            float s6[6] = {0.f, 0.f, 0.f, 0.f, 0.f, 0.f};
            for (int i = 0; i < 50; ++i) {
#pragma unroll
                for (int k = 0; k < 3; ++k)
                    s6[k] += g_part_fine[((size_t)t * 50 + i) * 3 + k];
            }
            for (int i = 0; i < 5; ++i) {
#pragma unroll
                for (int k = 0; k < 3; ++k)
                    s6[3 + k] += g_part_coarse[((size_t)t * 5 + i) * 3 + k];
            }
            const float inv = 1.0f / 6400.0f;
            float a[4][4];
            a[0][0] = a[1][1] = a[2][2] = a[3][3] = 1.0f;
            a[0][1] = a[1][0] = s6[0] * inv;
            a[0][2] = a[2][0] = s6[1] * inv;
            a[0][3] = a[3][0] = s6[2] * inv;
            a[1][2] = a[2][1] = s6[3] * inv;
            a[1][3] = a[3][1] = s6[4] * inv;
            a[2][3] = a[3][2] = s6[5] * inv;
            for (int i = 0; i < 4; ++i) {
                float m = a[i][0];
                for (int j = 1; j < 4; ++j) m = fmaxf(m, a[i][j]);
                float e[4], sum = 0.f;
                for (int j = 0; j < 4; ++j) { e[j] = expf(a[i][j] - m); sum += e[j]; }
                for (int j = 0; j < 4; ++j) out[t * 16 + i * 4 + j] = e[j] / sum;
            }
        }
        if (t == 0) {           // reset for next graph replay
            g_ticket = 0;
            g_wdone = 0;
            g_small_done = 0;
        }
    }
}

// ---------------------------------------------------------------------------
extern "C" void kernel_launch(void* const* d_in, const int* in_sizes, int n_in,
                              void* d_out, int out_size)
{
    const float* f[4]  = {nullptr, nullptr, nullptr, nullptr};
    const float* w[4]  = {nullptr, nullptr, nullptr, nullptr};
    const float* bs[4] = {nullptr, nullptr, nullptr, nullptr};
    int wi = 0, bi = 0;
    for (int i = 0; i < n_in; ++i) {
        long sz = in_sizes[i];
        const float* p = (const float*)d_in[i];
        if      (sz == 65536)    { if (wi < 4) w[wi++]  = p; }
        else if (sz == 256)      { if (bi < 4) bs[bi++] = p; }
        else if (sz == 13107200) f[0] = p;   // 8*256*6400
        else if (sz == 3276800)  f[1] = p;   // 8*256*1600
        else if (sz == 819200)   f[2] = p;   // 8*256*400
        else if (sz == 204800)   f[3] = p;   // 8*256*100
    }

    cudaFuncSetAttribute(mega, cudaFuncAttributeMaxDynamicSharedMemorySize, GEMM_SMEM);
    mega<<<588, 512, GEMM_SMEM>>>(f[0], f[1], f[2], f[3],
                                  w[0], w[1], w[2], w[3],
                                  bs[0], bs[1], bs[2], bs[3],
                                  (float*)d_out);
}

// round 15
// speedup vs baseline: 1.2044x; 1.2044x over previous
#include <cuda_runtime.h>
#include <cuda_bf16.h>
#include <cstdint>
#include <math.h>

#define C256 256

// ---------------------------------------------------------------------------
// Scratch (device globals; no allocations allowed)
// ---------------------------------------------------------------------------
__device__ __nv_bfloat16 g_Wh[4][C256 * C256];
__device__ __nv_bfloat16 g_P1[8 * 1600 * C256];
__device__ __nv_bfloat16 g_P2[8 *  400 * C256];
__device__ __nv_bfloat16 g_P3[8 *  100 * C256];
__device__ float g_part_fine[8 * 50 * 3];
__device__ float g_part_coarse[8 * 5 * 3];
__device__ unsigned int g_wdone;       // converters done (4) — within launch A
__device__ unsigned int g_ticket;      // fine+coarse tickets (440) — launch B

__device__ __forceinline__ uint32_t smem_to_u32(const void* p) {
    uint32_t a;
    asm("{ .reg .u64 t; cvta.to.shared.u64 t, %1; cvt.u32.u64 %0, t; }"
        : "=r"(a) : "l"(p));
    return a;
}

#define CP16(dst, src, sz) \
    asm volatile("cp.async.cg.shared.global [%0], [%1], 16, %2;" \
                 :: "r"(dst), "l"(src), "r"(sz))
#define CP_COMMIT() asm volatile("cp.async.commit_group;" ::: "memory")
#define CP_WAIT0()  asm volatile("cp.async.wait_group 0;" ::: "memory")

__device__ __forceinline__ void ldx4(uint32_t* r, uint32_t addr) {
    asm volatile("ldmatrix.sync.aligned.m8n8.x4.shared.b16 {%0,%1,%2,%3}, [%4];"
                 : "=r"(r[0]), "=r"(r[1]), "=r"(r[2]), "=r"(r[3]) : "r"(addr));
}
__device__ __forceinline__ void ldx4t(uint32_t* r, uint32_t addr) {
    asm volatile("ldmatrix.sync.aligned.m8n8.x4.trans.shared.b16 {%0,%1,%2,%3}, [%4];"
                 : "=r"(r[0]), "=r"(r[1]), "=r"(r[2]), "=r"(r[3]) : "r"(addr));
}
__device__ __forceinline__ void mma16816(float* d, const uint32_t* a, const uint32_t* b) {
    asm volatile("mma.sync.aligned.m16n8k16.row.col.f32.bf16.bf16.f32 "
                 "{%0,%1,%2,%3}, {%4,%5,%6,%7}, {%8,%9}, {%0,%1,%2,%3};"
                 : "+f"(d[0]), "+f"(d[1]), "+f"(d[2]), "+f"(d[3])
                 : "r"(a[0]), "r"(a[1]), "r"(a[2]), "r"(a[3]), "r"(b[0]), "r"(b[1]));
}
__device__ __forceinline__ void exp8(uint4 u, float* f) {
    f[0] = __uint_as_float(u.x << 16); f[1] = __uint_as_float(u.x & 0xffff0000u);
    f[2] = __uint_as_float(u.y << 16); f[3] = __uint_as_float(u.y & 0xffff0000u);
    f[4] = __uint_as_float(u.z << 16); f[5] = __uint_as_float(u.z & 0xffff0000u);
    f[6] = __uint_as_float(u.w << 16); f[7] = __uint_as_float(u.w & 0xffff0000u);
}

#define SPIN_ON(ctr, target) do {                                             \
        if (threadIdx.x == 0) {                                               \
            while (atomicAdd(&(ctr), 0u) < (target)) { }                      \
            __threadfence();                                                  \
        }                                                                     \
        __syncthreads();                                                      \
    } while (0)

// ---------------------------------------------------------------------------
// GEMM tile config: BM=256, BN=128, BK=32, 512 threads (4x4 warps).
// ---------------------------------------------------------------------------
#define A_ROWB 80u
#define A_TILE (256u * A_ROWB)
#define B_ROWB 272u
#define B_TILE (32u * B_ROWB)
#define STAGE  (A_TILE + B_TILE)
#define EP_ROWB 528u
#define GEMM_SMEM (128u * EP_ROWB)      // 67584 > 2*STAGE

#define GEMM_DECLS()                                                           \
    const uint32_t sb = smem_to_u32(sm);                                       \
    const int tid = threadIdx.x;                                               \
    const int wid = tid >> 5, lane = tid & 31;                                 \
    const int arow = tid >> 1;                                                 \
    const int c2   = (tid & 1) * 2;                                            \
    const uint32_t aOff = arow * A_ROWB + c2 * 16;                             \
    const int cloc = tid >> 4;                                                 \
    const int lcol = (tid & 15) * 8;                                           \
    const int r8 = lane & 7, sel = lane >> 3;                                  \
    const int warp_m = wid >> 2, warp_n = wid & 3;                             \
    const uint32_t aRel = (uint32_t)((warp_m * 64 + r8 + (sel & 1) * 8) * A_ROWB \
                                     + (sel >> 1) * 16);                       \
    const uint32_t bRel = (uint32_t)(A_TILE                                    \
                          + ((sel & 1) * 8 + r8) * B_ROWB                      \
                          + (warp_n * 32 + (sel >> 1) * 8) * 2)

#define ISSUE_A(kc, st) do {                                                  \
        const uint32_t base = sb + (uint32_t)(st) * STAGE;                    \
        const int ko = (kc) * 64;                                             \
        CP16(base + aOff,      srcAh + ko,      16u);                         \
        CP16(base + aOff + 16, srcAh + ko + 16, 16u);                         \
        CP_COMMIT();                                                          \
    } while (0)

#define STS_B(st) do {                                                        \
        char* bp = sm + (size_t)(st) * STAGE + A_TILE                         \
                   + (size_t)cloc * B_ROWB + lcol * 2;                        \
        uint4 p0;                                                             \
        __nv_bfloat162 t;                                                     \
        t = __float22bfloat162_rn(make_float2(v[0].x, v[0].y)); p0.x = *(uint32_t*)&t; \
        t = __float22bfloat162_rn(make_float2(v[0].z, v[0].w)); p0.y = *(uint32_t*)&t; \
        t = __float22bfloat162_rn(make_float2(v[1].x, v[1].y)); p0.z = *(uint32_t*)&t; \
        t = __float22bfloat162_rn(make_float2(v[1].z, v[1].w)); p0.w = *(uint32_t*)&t; \
        *(uint4*)(bp) = p0;                                                   \
    } while (0)

#define GEMM_MAINLOOP(LDG_B_MACRO)                                            \
    float acc[4][4][4];                                                       \
    _Pragma("unroll")                                                         \
    for (int i = 0; i < 4; ++i)                                               \
        _Pragma("unroll")                                                     \
        for (int j = 0; j < 4; ++j)                                           \
            _Pragma("unroll")                                                 \
            for (int k = 0; k < 4; ++k) acc[i][j][k] = 0.f;                   \
    LDG_B_MACRO(0);                                                           \
    STS_B(0);                                                                 \
    ISSUE_A(0, 0);                                                            \
    CP_WAIT0();                                                               \
    __syncthreads();                                                          \
    for (int kc = 0; kc < 8; ++kc) {                                          \
        const int st = kc & 1;                                                \
        if (kc < 7) { LDG_B_MACRO(kc + 1); ISSUE_A(kc + 1, st ^ 1); }         \
        const uint32_t stage = sb + (uint32_t)st * STAGE;                     \
        _Pragma("unroll")                                                     \
        for (int ks = 0; ks < 2; ++ks) {                                      \
            uint32_t bf[8];                                                   \
            ldx4t(bf,     stage + bRel + ks * 16 * B_ROWB);                   \
            ldx4t(bf + 4, stage + bRel + ks * 16 * B_ROWB + 32);              \
            uint32_t af[4];                                                   \
            _Pragma("unroll")                                                 \
            for (int mt = 0; mt < 4; ++mt) {                                  \
                ldx4(af, stage + aRel + ks * 32 + mt * 16 * A_ROWB);          \
                _Pragma("unroll")                                             \
                for (int nt = 0; nt < 4; ++nt)                                \
                    mma16816(acc[mt][nt], af, bf + (nt >> 1) * 4 + (nt & 1) * 2); \
            }                                                                 \
        }                                                                     \
        if (kc < 7) { STS_B(st ^ 1); CP_WAIT0(); }                            \
        __syncthreads();                                                      \
    }

#define GEMM_STAGE_EP()                                                       \
    {                                                                         \
        float bv[4][2];                                                       \
        _Pragma("unroll")                                                     \
        for (int mt = 0; mt < 4; ++mt) {                                      \
            const int m = warp_m * 64 + mt * 16 + (lane >> 2);                \
            bv[mt][0] = bias[m];                                              \
            bv[mt][1] = bias[m + 8];                                          \
        }                                                                     \
        __nv_bfloat16* ep = (__nv_bfloat16*)sm;                               \
        _Pragma("unroll")                                                     \
        for (int mt = 0; mt < 4; ++mt) {                                      \
            const int m = warp_m * 64 + mt * 16 + (lane >> 2);                \
            _Pragma("unroll")                                                 \
            for (int nt = 0; nt < 4; ++nt) {                                  \
                const int n = warp_n * 32 + nt * 8 + (lane & 3) * 2;          \
                ep[(size_t)n       * 264 + m]     = __float2bfloat16(acc[mt][nt][0] + bv[mt][0]); \
                ep[(size_t)(n + 1) * 264 + m]     = __float2bfloat16(acc[mt][nt][1] + bv[mt][0]); \
                ep[(size_t)n       * 264 + m + 8] = __float2bfloat16(acc[mt][nt][2] + bv[mt][1]); \
                ep[(size_t)(n + 1) * 264 + m + 8] = __float2bfloat16(acc[mt][nt][3] + bv[mt][1]); \
            }                                                                 \
        }                                                                     \
        __syncthreads();                                                      \
    }

// ---------------------------------------------------------------------------
// Launch A: 148 blocks (one full wave — co-residency guaranteed).
//   0..3   : W->bf16 converters
//   4..147 : small gemms (scales 1..3), spin on converters
// ---------------------------------------------------------------------------
__global__ __launch_bounds__(512, 1)
void small_conv(const float* __restrict__ f1, const float* __restrict__ f2,
                const float* __restrict__ f3,
                const float* __restrict__ w0, const float* __restrict__ w1,
                const float* __restrict__ w2, const float* __restrict__ w3,
                const float* __restrict__ b1, const float* __restrict__ b2,
                const float* __restrict__ b3)
{
    extern __shared__ char sm[];
    const int id = blockIdx.x;

    if (id < 4) {
        const float* w = (id == 0) ? w0 : (id == 1) ? w1 : (id == 2) ? w2 : w3;
        for (int i = threadIdx.x; i < 16384; i += 512) {
            const float4 v = ((const float4*)w)[i];
            __nv_bfloat162 lo = __float22bfloat162_rn(make_float2(v.x, v.y));
            __nv_bfloat162 hi = __float22bfloat162_rn(make_float2(v.z, v.w));
            uint2 pk;
            pk.x = *(uint32_t*)&lo;
            pk.y = *(uint32_t*)&hi;
            ((uint2*)g_Wh[id])[i] = pk;
        }
        __syncthreads();
        if (threadIdx.x == 0) { __threadfence(); atomicAdd(&g_wdone, 1u); }
        return;
    }

    GEMM_DECLS();
    const int sid = id - 4;
    int s, off, L;
    const float* F;
    const float* bias;
    __nv_bfloat16* P;
    if (sid < 104)      { s = 1; off = 0;   L = 1600; F = f1; bias = b1; P = g_P1; }
    else if (sid < 136) { s = 2; off = 104; L = 400;  F = f2; bias = b2; P = g_P2; }
    else                { s = 3; off = 136; L = 100;  F = f3; bias = b3; P = g_P3; }
    const int local = sid - off;
    const int l0    = (local >> 3) * 128;
    const int batch = local & 7;

    const float* Fb = F + (size_t)batch * C256 * L;
    __nv_bfloat16* Pb = P + (size_t)batch * L * C256;
    const char* srcAh = (const char*)(g_Wh[s] + (size_t)arow * C256) + c2 * 16;

    SPIN_ON(g_wdone, 4u);

    float4 v[2];
#define LDG_BS(kc) do {                                                       \
        const int ch = (kc) * 32 + cloc;                                      \
        const float* rp = Fb + (size_t)ch * L + l0 + lcol;                    \
        _Pragma("unroll")                                                     \
        for (int i = 0; i < 2; ++i)                                           \
            v[i] = (l0 + lcol + i * 4 < L) ? *(const float4*)(rp + i * 4)     \
                                           : make_float4(0.f, 0.f, 0.f, 0.f); \
    } while (0)

    GEMM_MAINLOOP(LDG_BS);
    GEMM_STAGE_EP();

    const int n = tid >> 2, quarter = tid & 3;
    if (l0 + n < L) {
        const uint4* src = (const uint4*)((const char*)sm + (size_t)n * EP_ROWB + quarter * 128);
        uint4* dst = (uint4*)(Pb + (size_t)(l0 + n) * C256 + quarter * 64);
#pragma unroll
        for (int i = 0; i < 8; ++i) dst[i] = src[i];
    }
#undef LDG_BS
}

// ---------------------------------------------------------------------------
// Launch B: 440 blocks.
//   0..39   : coarse pair sums (wave-1 riders)
//   40..439 : scale-0 gemm + fused fine cosine (shared coarse-vector loads)
//   last ticket: final softmax + counter reset
// ---------------------------------------------------------------------------
__global__ __launch_bounds__(512, 1)
void gemm0_fused(const float* __restrict__ f0, const float* __restrict__ b0,
                 float* __restrict__ out)
{
    extern __shared__ char sm[];
    __shared__ float sh2[16][3];
    __shared__ unsigned int sh_last;
    const int id = blockIdx.x;

    if (id >= 40) {
        GEMM_DECLS();
        const int fid   = id - 40;           // 0..399
        const int l0    = (fid >> 3) * 128;
        const int batch = fid & 7;
        const float* Fb = f0 + (size_t)batch * C256 * 6400;
        const float* bias = b0;
        const char* srcAh = (const char*)(g_Wh[0] + (size_t)arow * C256) + c2 * 16;

        float4 v[2];
#define LDG_B0(kc) do {                                                       \
        const int ch = (kc) * 32 + cloc;                                      \
        const float* rp = Fb + (size_t)ch * 6400 + l0 + lcol;                 \
        v[0] = *(const float4*)(rp);                                          \
        v[1] = *(const float4*)(rp + 4);                                      \
    } while (0)

        GEMM_MAINLOOP(LDG_B0);
        GEMM_STAGE_EP();

        // ---- fine cosine: warp = 8 consecutive pixels (8-aligned, same row)
        //      shared loads: 1x x3, 2x x2, 4x x1 per warp ----
        const int lb  = l0 + wid * 8;        // first pixel of this warp
        const int h   = lb / 80;
        const int w8  = lb - h * 80;         // multiple of 8
        float f3v[8], f2v[2][8], f1v[4][8];
        {
            const uint4 u3 = ((const uint4*)(g_P3 + (size_t)(batch * 100 + (h >> 3) * 10 + (w8 >> 3)) * C256))[lane];
            exp8(u3, f3v);
            const size_t b2i = (size_t)(batch * 400 + (h >> 2) * 20 + (w8 >> 2));
            const uint4 u2a = ((const uint4*)(g_P2 + b2i * C256))[lane];
            const uint4 u2b = ((const uint4*)(g_P2 + (b2i + 1) * C256))[lane];
            exp8(u2a, f2v[0]);
            exp8(u2b, f2v[1]);
            const size_t b1i = (size_t)(batch * 1600 + (h >> 1) * 40 + (w8 >> 1));
#pragma unroll
            for (int g1 = 0; g1 < 4; ++g1) {
                const uint4 u1 = ((const uint4*)(g_P1 + (b1i + g1) * C256))[lane];
                exp8(u1, f1v[g1]);
            }
        }
        // batched norms: d[0..3]=d11 g1=0..3, d[4..5]=d22, d[6]=d33
        float nd[7];
#pragma unroll
        for (int k = 0; k < 7; ++k) nd[k] = 0.f;
#pragma unroll
        for (int e = 0; e < 8; ++e) {
            nd[0] += f1v[0][e] * f1v[0][e];
            nd[1] += f1v[1][e] * f1v[1][e];
            nd[2] += f1v[2][e] * f1v[2][e];
            nd[3] += f1v[3][e] * f1v[3][e];
            nd[4] += f2v[0][e] * f2v[0][e];
            nd[5] += f2v[1][e] * f2v[1][e];
            nd[6] += f3v[e] * f3v[e];
        }
#pragma unroll
        for (int off = 16; off > 0; off >>= 1) {
#pragma unroll
            for (int k = 0; k < 7; ++k)
                nd[k] += __shfl_xor_sync(0xFFFFFFFFu, nd[k], off);
        }
        const float nn1[4] = {sqrtf(nd[0]), sqrtf(nd[1]), sqrtf(nd[2]), sqrtf(nd[3])};
        const float nn2[2] = {sqrtf(nd[4]), sqrtf(nd[5])};
        const float nn3    = sqrtf(nd[6]);

        float a01 = 0.f, a02 = 0.f, a03 = 0.f;
#pragma unroll
        for (int p = 0; p < 8; ++p) {
            const int g1 = p >> 1, g2 = p >> 2;
            const uint4 u0 = *(const uint4*)(sm + (size_t)(wid * 8 + p) * EP_ROWB + lane * 16);
            float f0v[8];
            exp8(u0, f0v);
            float d[4];
#pragma unroll
            for (int k = 0; k < 4; ++k) d[k] = 0.f;
#pragma unroll
            for (int e = 0; e < 8; ++e) {
                d[0] += f0v[e] * f0v[e];
                d[1] += f0v[e] * f1v[g1][e];
                d[2] += f0v[e] * f2v[g2][e];
                d[3] += f0v[e] * f3v[e];
            }
#pragma unroll
            for (int off = 16; off > 0; off >>= 1) {
#pragma unroll
                for (int k = 0; k < 4; ++k)
                    d[k] += __shfl_xor_sync(0xFFFFFFFFu, d[k], off);
            }
            const float n0 = sqrtf(d[0]);
            a01 += d[1] / fmaxf(n0 * nn1[g1], 1e-8f);
            a02 += d[2] / fmaxf(n0 * nn2[g2], 1e-8f);
            a03 += d[3] / fmaxf(n0 * nn3, 1e-8f);
        }
        if (lane == 0) { sh2[wid][0] = a01; sh2[wid][1] = a02; sh2[wid][2] = a03; }
        __syncthreads();
        if (tid == 0) {
            float* dst = &g_part_fine[((size_t)batch * 50 + (fid >> 3)) * 3];
#pragma unroll
            for (int k = 0; k < 3; ++k) {
                float ss = 0.f;
#pragma unroll
                for (int i = 0; i < 16; ++i) ss += sh2[i][k];
                dst[k] = ss;
            }
        }
#undef LDG_B0
    } else {
        // ---- coarse pairs (P1..P3 ready via stream order) ----
        const int tid = threadIdx.x;
        const int wid = tid >> 5, lane = tid & 31;
        const int batch = id / 5;
        const int seg   = id - batch * 5;   // 0..4
        float a12 = 0.f, a13 = 0.f, a23 = 0.f;
        for (int i = 0; i < 20; ++i) {
            const int loc = seg * 320 + wid * 20 + i;
            const int h1 = loc / 40;
            const int w1 = loc - h1 * 40;
            const uint4 u1 = ((const uint4*)(g_P1 + (size_t)(batch * 1600 + loc) * C256))[lane];
            const uint4 u2 = ((const uint4*)(g_P2 + (size_t)(batch *  400 + (h1 >> 1) * 20 + (w1 >> 1)) * C256))[lane];
            const uint4 u3 = ((const uint4*)(g_P3 + (size_t)(batch *  100 + (h1 >> 2) * 10 + (w1 >> 2)) * C256))[lane];
            float e1[8], e2[8], e3[8];
            exp8(u1, e1); exp8(u2, e2); exp8(u3, e3);
            float d[6];
#pragma unroll
            for (int k = 0; k < 6; ++k) d[k] = 0.f;
#pragma unroll
            for (int e = 0; e < 8; ++e) {
                d[0] += e1[e] * e1[e];
                d[1] += e2[e] * e2[e];
                d[2] += e3[e] * e3[e];
                d[3] += e1[e] * e2[e];
                d[4] += e1[e] * e3[e];
                d[5] += e2[e] * e3[e];
            }
#pragma unroll
            for (int off = 16; off > 0; off >>= 1) {
#pragma unroll
                for (int k = 0; k < 6; ++k)
                    d[k] += __shfl_xor_sync(0xFFFFFFFFu, d[k], off);
            }
            if (lane == 0) {
                const float n1 = sqrtf(d[0]);
                const float n2 = sqrtf(d[1]);
                const float n3 = sqrtf(d[2]);
                a12 += d[3] / fmaxf(n1 * n2, 1e-8f);
                a13 += d[4] / fmaxf(n1 * n3, 1e-8f);
                a23 += d[5] / fmaxf(n2 * n3, 1e-8f);
            }
        }
        if (lane == 0) { sh2[wid][0] = a12 * 4.f; sh2[wid][1] = a13 * 4.f; sh2[wid][2] = a23 * 4.f; }
        __syncthreads();
        if (tid == 0) {
            float* dst = &g_part_coarse[((size_t)batch * 5 + seg) * 3];
#pragma unroll
            for (int k = 0; k < 3; ++k) {
                float ss = 0.f;
#pragma unroll
                for (int i = 0; i < 16; ++i) ss += sh2[i][k];
                dst[k] = ss;
            }
        }
    }

    // ---- ticket + final softmax ----
    __syncthreads();
    if (threadIdx.x == 0) {
        __threadfence();
        sh_last = (atomicAdd(&g_ticket, 1u) == 439u);
    }
    __syncthreads();
    if (sh_last) {
        __threadfence();
        const int t = threadIdx.x;
        if (t < 8) {
            float s6[6] = {0.f, 0.f, 0.f, 0.f, 0.f, 0.f};
            for (int i = 0; i < 50; ++i) {
#pragma unroll
                for (int k = 0; k < 3; ++k)
                    s6[k] += g_part_fine[((size_t)t * 50 + i) * 3 + k];
            }
            for (int i = 0; i < 5; ++i) {
#pragma unroll
                for (int k = 0; k < 3; ++k)
                    s6[3 + k] += g_part_coarse[((size_t)t * 5 + i) * 3 + k];
            }
            const float inv = 1.0f / 6400.0f;
            float a[4][4];
            a[0][0] = a[1][1] = a[2][2] = a[3][3] = 1.0f;
            a[0][1] = a[1][0] = s6[0] * inv;
            a[0][2] = a[2][0] = s6[1] * inv;
            a[0][3] = a[3][0] = s6[2] * inv;
            a[1][2] = a[2][1] = s6[3] * inv;
            a[1][3] = a[3][1] = s6[4] * inv;
            a[2][3] = a[3][2] = s6[5] * inv;
            for (int i = 0; i < 4; ++i) {
                float m = a[i][0];
                for (int j = 1; j < 4; ++j) m = fmaxf(m, a[i][j]);
                float e[4], sum = 0.f;
                for (int j = 0; j < 4; ++j) { e[j] = expf(a[i][j] - m); sum += e[j]; }
                for (int j = 0; j < 4; ++j) out[t * 16 + i * 4 + j] = e[j] / sum;
            }
        }
        if (t == 0) {            // reset for next graph replay
            g_ticket = 0;
            g_wdone = 0;
        }
    }
}

// ---------------------------------------------------------------------------
extern "C" void kernel_launch(void* const* d_in, const int* in_sizes, int n_in,
                              void* d_out, int out_size)
{
    const float* f[4]  = {nullptr, nullptr, nullptr, nullptr};
    const float* w[4]  = {nullptr, nullptr, nullptr, nullptr};
    const float* bs[4] = {nullptr, nullptr, nullptr, nullptr};
    int wi = 0, bi = 0;
    for (int i = 0; i < n_in; ++i) {
        long sz = in_sizes[i];
        const float* p = (const float*)d_in[i];
        if      (sz == 65536)    { if (wi < 4) w[wi++]  = p; }
        else if (sz == 256)      { if (bi < 4) bs[bi++] = p; }
        else if (sz == 13107200) f[0] = p;   // 8*256*6400
        else if (sz == 3276800)  f[1] = p;   // 8*256*1600
        else if (sz == 819200)   f[2] = p;   // 8*256*400
        else if (sz == 204800)   f[3] = p;   // 8*256*100
    }

    cudaFuncSetAttribute(small_conv,  cudaFuncAttributeMaxDynamicSharedMemorySize, GEMM_SMEM);
    cudaFuncSetAttribute(gemm0_fused, cudaFuncAttributeMaxDynamicSharedMemorySize, GEMM_SMEM);

    small_conv<<<148, 512, GEMM_SMEM>>>(f[1], f[2], f[3],
                                        w[0], w[1], w[2], w[3],
                                        bs[1], bs[2], bs[3]);
    gemm0_fused<<<440, 512, GEMM_SMEM>>>(f[0], bs[0], (float*)d_out);
}

// round 16
// speedup vs baseline: 1.3200x; 1.0960x over previous
#include <cuda_runtime.h>
#include <cuda_bf16.h>
#include <cstdint>
#include <math.h>

#define C256 256

// ---------------------------------------------------------------------------
// Scratch (device globals; no allocations allowed)
// ---------------------------------------------------------------------------
__device__ __nv_bfloat16 g_Wh[4][C256 * C256];
__device__ __nv_bfloat16 g_P1[8 * 1600 * C256];
__device__ __nv_bfloat16 g_P2[8 *  400 * C256];
__device__ __nv_bfloat16 g_P3[8 *  100 * C256];
__device__ float g_part_fine[8 * 50 * 3];
__device__ float g_part_coarse[8 * 5 * 3];
__device__ unsigned int g_wdone;       // converters done (4) — within launch A
__device__ unsigned int g_ticket;      // fine+coarse tickets (440) — launch B

__device__ __forceinline__ uint32_t smem_to_u32(const void* p) {
    uint32_t a;
    asm("{ .reg .u64 t; cvta.to.shared.u64 t, %1; cvt.u32.u64 %0, t; }"
        : "=r"(a) : "l"(p));
    return a;
}

#define CP16(dst, src, sz) \
    asm volatile("cp.async.cg.shared.global [%0], [%1], 16, %2;" \
                 :: "r"(dst), "l"(src), "r"(sz))
#define CP_COMMIT() asm volatile("cp.async.commit_group;" ::: "memory")
#define CP_WAIT1()  asm volatile("cp.async.wait_group 1;" ::: "memory")
#define CP_WAIT0()  asm volatile("cp.async.wait_group 0;" ::: "memory")

__device__ __forceinline__ void ldx4(uint32_t* r, uint32_t addr) {
    asm volatile("ldmatrix.sync.aligned.m8n8.x4.shared.b16 {%0,%1,%2,%3}, [%4];"
                 : "=r"(r[0]), "=r"(r[1]), "=r"(r[2]), "=r"(r[3]) : "r"(addr));
}
__device__ __forceinline__ void ldx4t(uint32_t* r, uint32_t addr) {
    asm volatile("ldmatrix.sync.aligned.m8n8.x4.trans.shared.b16 {%0,%1,%2,%3}, [%4];"
                 : "=r"(r[0]), "=r"(r[1]), "=r"(r[2]), "=r"(r[3]) : "r"(addr));
}
__device__ __forceinline__ void mma16816(float* d, const uint32_t* a, const uint32_t* b) {
    asm volatile("mma.sync.aligned.m16n8k16.row.col.f32.bf16.bf16.f32 "
                 "{%0,%1,%2,%3}, {%4,%5,%6,%7}, {%8,%9}, {%0,%1,%2,%3};"
                 : "+f"(d[0]), "+f"(d[1]), "+f"(d[2]), "+f"(d[3])
                 : "r"(a[0]), "r"(a[1]), "r"(a[2]), "r"(a[3]), "r"(b[0]), "r"(b[1]));
}
__device__ __forceinline__ void exp8(uint4 u, float* f) {
    f[0] = __uint_as_float(u.x << 16); f[1] = __uint_as_float(u.x & 0xffff0000u);
    f[2] = __uint_as_float(u.y << 16); f[3] = __uint_as_float(u.y & 0xffff0000u);
    f[4] = __uint_as_float(u.z << 16); f[5] = __uint_as_float(u.z & 0xffff0000u);
    f[6] = __uint_as_float(u.w << 16); f[7] = __uint_as_float(u.w & 0xffff0000u);
}

#define SPIN_ON(ctr, target) do {                                             \
        if (threadIdx.x == 0) {                                               \
            while (atomicAdd(&(ctr), 0u) < (target)) { }                      \
            __threadfence();                                                  \
        }                                                                     \
        __syncthreads();                                                      \
    } while (0)

// ---------------------------------------------------------------------------
// GEMM tile config: BM=256, BN=128, BK=32, 512 threads (4x4 warps), 3-stage.
// ---------------------------------------------------------------------------
#define A_ROWB 80u
#define A_TILE (256u * A_ROWB)
#define B_ROWB 272u
#define B_TILE (32u * B_ROWB)
#define STAGE  (A_TILE + B_TILE)        // 29184
#define EP_ROWB 528u
#define GEMM_SMEM (3u * STAGE)          // 87552 > 128*EP_ROWB (67584)

#define GEMM_DECLS()                                                           \
    const uint32_t sb = smem_to_u32(sm);                                       \
    const int tid = threadIdx.x;                                               \
    const int wid = tid >> 5, lane = tid & 31;                                 \
    const int arow = tid >> 1;                                                 \
    const int c2   = (tid & 1) * 2;                                            \
    const uint32_t aOff = arow * A_ROWB + c2 * 16;                             \
    const int cloc = tid >> 4;                                                 \
    const int lcol = (tid & 15) * 8;                                           \
    const int r8 = lane & 7, sel = lane >> 3;                                  \
    const int warp_m = wid >> 2, warp_n = wid & 3;                             \
    const uint32_t aRel = (uint32_t)((warp_m * 64 + r8 + (sel & 1) * 8) * A_ROWB \
                                     + (sel >> 1) * 16);                       \
    const uint32_t bRel = (uint32_t)(A_TILE                                    \
                          + ((sel & 1) * 8 + r8) * B_ROWB                      \
                          + (warp_n * 32 + (sel >> 1) * 8) * 2)

#define ISSUE_A(kc, st) do {                                                  \
        const uint32_t base = sb + (uint32_t)(st) * STAGE;                    \
        const int ko = (kc) * 64;                                             \
        CP16(base + aOff,      srcAh + ko,      16u);                         \
        CP16(base + aOff + 16, srcAh + ko + 16, 16u);                         \
        CP_COMMIT();                                                          \
    } while (0)

#define STS_B2(st, vv) do {                                                   \
        char* bp = sm + (size_t)(st) * STAGE + A_TILE                         \
                   + (size_t)cloc * B_ROWB + lcol * 2;                        \
        uint4 p0;                                                             \
        __nv_bfloat162 t;                                                     \
        t = __float22bfloat162_rn(make_float2((vv)[0].x, (vv)[0].y)); p0.x = *(uint32_t*)&t; \
        t = __float22bfloat162_rn(make_float2((vv)[0].z, (vv)[0].w)); p0.y = *(uint32_t*)&t; \
        t = __float22bfloat162_rn(make_float2((vv)[1].x, (vv)[1].y)); p0.z = *(uint32_t*)&t; \
        t = __float22bfloat162_rn(make_float2((vv)[1].z, (vv)[1].w)); p0.w = *(uint32_t*)&t; \
        *(uint4*)(bp) = p0;                                                   \
    } while (0)

// 3-stage mainloop: B loaded 2 chunks ahead (double reg buffer),
// cp.async A at wait_group 1 depth. Same k-order as 2-stage (bit-identical).
#define GEMM_MAINLOOP(LDG_B_MACRO)                                            \
    float acc[4][4][4];                                                       \
    _Pragma("unroll")                                                         \
    for (int i = 0; i < 4; ++i)                                               \
        _Pragma("unroll")                                                     \
        for (int j = 0; j < 4; ++j)                                           \
            _Pragma("unroll")                                                 \
            for (int k = 0; k < 4; ++k) acc[i][j][k] = 0.f;                   \
    float4 vbuf[2][2];                                                        \
    LDG_B_MACRO(0, vbuf[0]);                                                  \
    LDG_B_MACRO(1, vbuf[1]);                                                  \
    ISSUE_A(0, 0);                                                            \
    ISSUE_A(1, 1);                                                            \
    STS_B2(0, vbuf[0]);                                                       \
    STS_B2(1, vbuf[1]);                                                       \
    LDG_B_MACRO(2, vbuf[0]);                                                  \
    CP_WAIT1();                                                               \
    __syncthreads();                                                          \
    for (int kc = 0; kc < 8; ++kc) {                                          \
        const int st = kc % 3;                                                \
        if (kc < 6) ISSUE_A(kc + 2, (kc + 2) % 3);                            \
        if (kc < 5) LDG_B_MACRO(kc + 3, vbuf[(kc + 1) & 1]);                  \
        const uint32_t stage = sb + (uint32_t)st * STAGE;                     \
        _Pragma("unroll")                                                     \
        for (int ks = 0; ks < 2; ++ks) {                                      \
            uint32_t bf[8];                                                   \
            ldx4t(bf,     stage + bRel + ks * 16 * B_ROWB);                   \
            ldx4t(bf + 4, stage + bRel + ks * 16 * B_ROWB + 32);              \
            uint32_t af[4];                                                   \
            _Pragma("unroll")                                                 \
            for (int mt = 0; mt < 4; ++mt) {                                  \
                ldx4(af, stage + aRel + ks * 32 + mt * 16 * A_ROWB);          \
                _Pragma("unroll")                                             \
                for (int nt = 0; nt < 4; ++nt)                                \
                    mma16816(acc[mt][nt], af, bf + (nt >> 1) * 4 + (nt & 1) * 2); \
            }                                                                 \
        }                                                                     \
        if (kc < 6) { STS_B2((kc + 2) % 3, vbuf[kc & 1]); CP_WAIT1(); }       \
        else if (kc == 6) CP_WAIT0();                                         \
        __syncthreads();                                                      \
    }

#define GEMM_STAGE_EP()                                                       \
    {                                                                         \
        float bv[4][2];                                                       \
        _Pragma("unroll")                                                     \
        for (int mt = 0; mt < 4; ++mt) {                                      \
            const int m = warp_m * 64 + mt * 16 + (lane >> 2);                \
            bv[mt][0] = bias[m];                                              \
            bv[mt][1] = bias[m + 8];                                          \
        }                                                                     \
        __nv_bfloat16* ep = (__nv_bfloat16*)sm;                               \
        _Pragma("unroll")                                                     \
        for (int mt = 0; mt < 4; ++mt) {                                      \
            const int m = warp_m * 64 + mt * 16 + (lane >> 2);                \
            _Pragma("unroll")                                                 \
            for (int nt = 0; nt < 4; ++nt) {                                  \
                const int n = warp_n * 32 + nt * 8 + (lane & 3) * 2;          \
                ep[(size_t)n       * 264 + m]     = __float2bfloat16(acc[mt][nt][0] + bv[mt][0]); \
                ep[(size_t)(n + 1) * 264 + m]     = __float2bfloat16(acc[mt][nt][1] + bv[mt][0]); \
                ep[(size_t)n       * 264 + m + 8] = __float2bfloat16(acc[mt][nt][2] + bv[mt][1]); \
                ep[(size_t)(n + 1) * 264 + m + 8] = __float2bfloat16(acc[mt][nt][3] + bv[mt][1]); \
            }                                                                 \
        }                                                                     \
        __syncthreads();                                                      \
    }

// ---------------------------------------------------------------------------
// Launch A: 148 blocks (one full wave — co-residency guaranteed).
//   0..3   : W->bf16 converters
//   4..147 : small gemms (scales 1..3), spin on converters
// ---------------------------------------------------------------------------
__global__ __launch_bounds__(512, 1)
void small_conv(const float* __restrict__ f1, const float* __restrict__ f2,
                const float* __restrict__ f3,
                const float* __restrict__ w0, const float* __restrict__ w1,
                const float* __restrict__ w2, const float* __restrict__ w3,
                const float* __restrict__ b1, const float* __restrict__ b2,
                const float* __restrict__ b3)
{
    extern __shared__ char sm[];
    const int id = blockIdx.x;

    if (id < 4) {
        const float* w = (id == 0) ? w0 : (id == 1) ? w1 : (id == 2) ? w2 : w3;
        for (int i = threadIdx.x; i < 16384; i += 512) {
            const float4 v = ((const float4*)w)[i];
            __nv_bfloat162 lo = __float22bfloat162_rn(make_float2(v.x, v.y));
            __nv_bfloat162 hi = __float22bfloat162_rn(make_float2(v.z, v.w));
            uint2 pk;
            pk.x = *(uint32_t*)&lo;
            pk.y = *(uint32_t*)&hi;
            ((uint2*)g_Wh[id])[i] = pk;
        }
        __syncthreads();
        if (threadIdx.x == 0) { __threadfence(); atomicAdd(&g_wdone, 1u); }
        return;
    }

    GEMM_DECLS();
    const int sid = id - 4;
    int s, off, L;
    const float* F;
    const float* bias;
    __nv_bfloat16* P;
    if (sid < 104)      { s = 1; off = 0;   L = 1600; F = f1; bias = b1; P = g_P1; }
    else if (sid < 136) { s = 2; off = 104; L = 400;  F = f2; bias = b2; P = g_P2; }
    else                { s = 3; off = 136; L = 100;  F = f3; bias = b3; P = g_P3; }
    const int local = sid - off;
    const int l0    = (local >> 3) * 128;
    const int batch = local & 7;

    const float* Fb = F + (size_t)batch * C256 * L;
    __nv_bfloat16* Pb = P + (size_t)batch * L * C256;
    const char* srcAh = (const char*)(g_Wh[s] + (size_t)arow * C256) + c2 * 16;

    SPIN_ON(g_wdone, 4u);

#define LDG_BS(kc, vv) do {                                                   \
        const int ch = (kc) * 32 + cloc;                                      \
        const float* rp = Fb + (size_t)ch * L + l0 + lcol;                    \
        _Pragma("unroll")                                                     \
        for (int i = 0; i < 2; ++i)                                           \
            (vv)[i] = (l0 + lcol + i * 4 < L) ? *(const float4*)(rp + i * 4)  \
                                              : make_float4(0.f, 0.f, 0.f, 0.f); \
    } while (0)

    GEMM_MAINLOOP(LDG_BS);
    GEMM_STAGE_EP();

    const int n = tid >> 2, quarter = tid & 3;
    if (l0 + n < L) {
        const uint4* src = (const uint4*)((const char*)sm + (size_t)n * EP_ROWB + quarter * 128);
        uint4* dst = (uint4*)(Pb + (size_t)(l0 + n) * C256 + quarter * 64);
#pragma unroll
        for (int i = 0; i < 8; ++i) dst[i] = src[i];
    }
#undef LDG_BS
}

// ---------------------------------------------------------------------------
// Launch B: 440 blocks.
//   0..39   : coarse pair sums (wave-1 riders)
//   40..439 : scale-0 gemm + fused fine cosine (shared coarse-vector loads)
//   last ticket: final softmax + counter reset
// ---------------------------------------------------------------------------
__global__ __launch_bounds__(512, 1)
void gemm0_fused(const float* __restrict__ f0, const float* __restrict__ b0,
                 float* __restrict__ out)
{
    extern __shared__ char sm[];
    __shared__ float sh2[16][3];
    __shared__ unsigned int sh_last;
    const int id = blockIdx.x;

    if (id >= 40) {
        GEMM_DECLS();
        const int fid   = id - 40;           // 0..399
        const int l0    = (fid >> 3) * 128;
        const int batch = fid & 7;
        const float* Fb = f0 + (size_t)batch * C256 * 6400;
        const float* bias = b0;
        const char* srcAh = (const char*)(g_Wh[0] + (size_t)arow * C256) + c2 * 16;

#define LDG_B0(kc, vv) do {                                                   \
        const int ch = (kc) * 32 + cloc;                                      \
        const float* rp = Fb + (size_t)ch * 6400 + l0 + lcol;                 \
        (vv)[0] = *(const float4*)(rp);                                       \
        (vv)[1] = *(const float4*)(rp + 4);                                   \
    } while (0)

        GEMM_MAINLOOP(LDG_B0);
        GEMM_STAGE_EP();

        // ---- fine cosine: warp = 8 consecutive pixels (8-aligned, same row)
        //      shared loads: 1x x3, 2x x2, 4x x1 per warp; rsqrt normalization ----
        const int lb  = l0 + wid * 8;
        const int h   = lb / 80;
        const int w8  = lb - h * 80;
        float f3v[8], f2v[2][8], f1v[4][8];
        {
            const uint4 u3 = ((const uint4*)(g_P3 + (size_t)(batch * 100 + (h >> 3) * 10 + (w8 >> 3)) * C256))[lane];
            exp8(u3, f3v);
            const size_t b2i = (size_t)(batch * 400 + (h >> 2) * 20 + (w8 >> 2));
            const uint4 u2a = ((const uint4*)(g_P2 + b2i * C256))[lane];
            const uint4 u2b = ((const uint4*)(g_P2 + (b2i + 1) * C256))[lane];
            exp8(u2a, f2v[0]);
            exp8(u2b, f2v[1]);
            const size_t b1i = (size_t)(batch * 1600 + (h >> 1) * 40 + (w8 >> 1));
#pragma unroll
            for (int g1 = 0; g1 < 4; ++g1) {
                const uint4 u1 = ((const uint4*)(g_P1 + (b1i + g1) * C256))[lane];
                exp8(u1, f1v[g1]);
            }
        }
        float nd[7];
#pragma unroll
        for (int k = 0; k < 7; ++k) nd[k] = 0.f;
#pragma unroll
        for (int e = 0; e < 8; ++e) {
            nd[0] += f1v[0][e] * f1v[0][e];
            nd[1] += f1v[1][e] * f1v[1][e];
            nd[2] += f1v[2][e] * f1v[2][e];
            nd[3] += f1v[3][e] * f1v[3][e];
            nd[4] += f2v[0][e] * f2v[0][e];
            nd[5] += f2v[1][e] * f2v[1][e];
            nd[6] += f3v[e] * f3v[e];
        }
#pragma unroll
        for (int off = 16; off > 0; off >>= 1) {
#pragma unroll
            for (int k = 0; k < 7; ++k)
                nd[k] += __shfl_xor_sync(0xFFFFFFFFu, nd[k], off);
        }
        const float rn1[4] = {rsqrtf(nd[0]), rsqrtf(nd[1]), rsqrtf(nd[2]), rsqrtf(nd[3])};
        const float rn2[2] = {rsqrtf(nd[4]), rsqrtf(nd[5])};
        const float rn3    = rsqrtf(nd[6]);

        float a01 = 0.f, a02 = 0.f, a03 = 0.f;
#pragma unroll
        for (int p = 0; p < 8; ++p) {
            const int g1 = p >> 1, g2 = p >> 2;
            const uint4 u0 = *(const uint4*)(sm + (size_t)(wid * 8 + p) * EP_ROWB + lane * 16);
            float f0v[8];
            exp8(u0, f0v);
            float d[4];
#pragma unroll
            for (int k = 0; k < 4; ++k) d[k] = 0.f;
#pragma unroll
            for (int e = 0; e < 8; ++e) {
                d[0] += f0v[e] * f0v[e];
                d[1] += f0v[e] * f1v[g1][e];
                d[2] += f0v[e] * f2v[g2][e];
                d[3] += f0v[e] * f3v[e];
            }
#pragma unroll
            for (int off = 16; off > 0; off >>= 1) {
#pragma unroll
                for (int k = 0; k < 4; ++k)
                    d[k] += __shfl_xor_sync(0xFFFFFFFFu, d[k], off);
            }
            const float r0 = rsqrtf(d[0]);
            a01 += d[1] * r0 * rn1[g1];
            a02 += d[2] * r0 * rn2[g2];
            a03 += d[3] * r0 * rn3;
        }
        if (lane == 0) { sh2[wid][0] = a01; sh2[wid][1] = a02; sh2[wid][2] = a03; }
        __syncthreads();
        if (tid == 0) {
            float* dst = &g_part_fine[((size_t)batch * 50 + (fid >> 3)) * 3];
#pragma unroll
            for (int k = 0; k < 3; ++k) {
                float ss = 0.f;
#pragma unroll
                for (int i = 0; i < 16; ++i) ss += sh2[i][k];
                dst[k] = ss;
            }
        }
#undef LDG_B0
    } else {
        // ---- coarse pairs (P1..P3 ready via stream order) ----
        const int tid = threadIdx.x;
        const int wid = tid >> 5, lane = tid & 31;
        const int batch = id / 5;
        const int seg   = id - batch * 5;   // 0..4
        float a12 = 0.f, a13 = 0.f, a23 = 0.f;
        for (int i = 0; i < 20; ++i) {
            const int loc = seg * 320 + wid * 20 + i;
            const int h1 = loc / 40;
            const int w1 = loc - h1 * 40;
            const uint4 u1 = ((const uint4*)(g_P1 + (size_t)(batch * 1600 + loc) * C256))[lane];
            const uint4 u2 = ((const uint4*)(g_P2 + (size_t)(batch *  400 + (h1 >> 1) * 20 + (w1 >> 1)) * C256))[lane];
            const uint4 u3 = ((const uint4*)(g_P3 + (size_t)(batch *  100 + (h1 >> 2) * 10 + (w1 >> 2)) * C256))[lane];
            float e1[8], e2[8], e3[8];
            exp8(u1, e1); exp8(u2, e2); exp8(u3, e3);
            float d[6];
#pragma unroll
            for (int k = 0; k < 6; ++k) d[k] = 0.f;
#pragma unroll
            for (int e = 0; e < 8; ++e) {
                d[0] += e1[e] * e1[e];
                d[1] += e2[e] * e2[e];
                d[2] += e3[e] * e3[e];
                d[3] += e1[e] * e2[e];
                d[4] += e1[e] * e3[e];
                d[5] += e2[e] * e3[e];
            }
#pragma unroll
            for (int off = 16; off > 0; off >>= 1) {
#pragma unroll
                for (int k = 0; k < 6; ++k)
                    d[k] += __shfl_xor_sync(0xFFFFFFFFu, d[k], off);
            }
            if (lane == 0) {
                const float r1 = rsqrtf(d[0]);
                const float r2 = rsqrtf(d[1]);
                const float r3 = rsqrtf(d[2]);
                a12 += d[3] * r1 * r2;
                a13 += d[4] * r1 * r3;
                a23 += d[5] * r2 * r3;
            }
        }
        if (lane == 0) { sh2[wid][0] = a12 * 4.f; sh2[wid][1] = a13 * 4.f; sh2[wid][2] = a23 * 4.f; }
        __syncthreads();
        if (tid == 0) {
            float* dst = &g_part_coarse[((size_t)batch * 5 + seg) * 3];
#pragma unroll
            for (int k = 0; k < 3; ++k) {
                float ss = 0.f;
#pragma unroll
                for (int i = 0; i < 16; ++i) ss += sh2[i][k];
                dst[k] = ss;
            }
        }
    }

    // ---- ticket + final softmax ----
    __syncthreads();
    if (threadIdx.x == 0) {
        __threadfence();
        sh_last = (atomicAdd(&g_ticket, 1u) == 439u);
    }
    __syncthreads();
    if (sh_last) {
        __threadfence();
        const int t = threadIdx.x;
        if (t < 8) {
            float s6[6] = {0.f, 0.f, 0.f, 0.f, 0.f, 0.f};
            for (int i = 0; i < 50; ++i) {
#pragma unroll
                for (int k = 0; k < 3; ++k)
                    s6[k] += g_part_fine[((size_t)t * 50 + i) * 3 + k];
            }
            for (int i = 0; i < 5; ++i) {
#pragma unroll
                for (int k = 0; k < 3; ++k)
                    s6[3 + k] += g_part_coarse[((size_t)t * 5 + i) * 3 + k];
            }
            const float inv = 1.0f / 6400.0f;
            float a[4][4];
            a[0][0] = a[1][1] = a[2][2] = a[3][3] = 1.0f;
            a[0][1] = a[1][0] = s6[0] * inv;
            a[0][2] = a[2][0] = s6[1] * inv;
            a[0][3] = a[3][0] = s6[2] * inv;
            a[1][2] = a[2][1] = s6[3] * inv;
            a[1][3] = a[3][1] = s6[4] * inv;
            a[2][3] = a[3][2] = s6[5] * inv;
            for (int i = 0; i < 4; ++i) {
                float m = a[i][0];
                for (int j = 1; j < 4; ++j) m = fmaxf(m, a[i][j]);
                float e[4], sum = 0.f;
                for (int j = 0; j < 4; ++j) { e[j] = expf(a[i][j] - m); sum += e[j]; }
                for (int j = 0; j < 4; ++j) out[t * 16 + i * 4 + j] = e[j] / sum;
            }
        }
        if (t == 0) {            // reset for next graph replay
            g_ticket = 0;
            g_wdone = 0;
        }
    }
}

// ---------------------------------------------------------------------------
extern "C" void kernel_launch(void* const* d_in, const int* in_sizes, int n_in,
                              void* d_out, int out_size)
{
    const float* f[4]  = {nullptr, nullptr, nullptr, nullptr};
    const float* w[4]  = {nullptr, nullptr, nullptr, nullptr};
    const float* bs[4] = {nullptr, nullptr, nullptr, nullptr};
    int wi = 0, bi = 0;
    for (int i = 0; i < n_in; ++i) {
        long sz = in_sizes[i];
        const float* p = (const float*)d_in[i];
        if      (sz == 65536)    { if (wi < 4) w[wi++]  = p; }
        else if (sz == 256)      { if (bi < 4) bs[bi++] = p; }
        else if (sz == 13107200) f[0] = p;   // 8*256*6400
        else if (sz == 3276800)  f[1] = p;   // 8*256*1600
        else if (sz == 819200)   f[2] = p;   // 8*256*400
        else if (sz == 204800)   f[3] = p;   // 8*256*100
    }

    cudaFuncSetAttribute(small_conv,  cudaFuncAttributeMaxDynamicSharedMemorySize, GEMM_SMEM);
    cudaFuncSetAttribute(gemm0_fused, cudaFuncAttributeMaxDynamicSharedMemorySize, GEMM_SMEM);

    small_conv<<<148, 512, GEMM_SMEM>>>(f[1], f[2], f[3],
                                        w[0], w[1], w[2], w[3],
                                        bs[1], bs[2], bs[3]);
    gemm0_fused<<<440, 512, GEMM_SMEM>>>(f[0], bs[0], (float*)d_out);
}

// round 17
// speedup vs baseline: 1.3643x; 1.0336x over previous
#include <cuda_runtime.h>
#include <cuda_bf16.h>
#include <cstdint>
#include <math.h>

#define C256 256

// ---------------------------------------------------------------------------
// Scratch (device globals; no allocations allowed)
// ---------------------------------------------------------------------------
__device__ __nv_bfloat16 g_Wh[4][C256 * C256];
__device__ __nv_bfloat16 g_P1[8 * 1600 * C256];
__device__ __nv_bfloat16 g_P2[8 *  400 * C256];
__device__ __nv_bfloat16 g_P3[8 *  100 * C256];
__device__ float g_part_fine[8 * 50 * 3];
__device__ float g_part_coarse[8 * 5 * 3];
__device__ unsigned int g_wdone;       // converters done (4) — within launch A
__device__ unsigned int g_ticket;      // fine+coarse tickets (440) — launch B

__device__ __forceinline__ uint32_t smem_to_u32(const void* p) {
    uint32_t a;
    asm("{ .reg .u64 t; cvta.to.shared.u64 t, %1; cvt.u32.u64 %0, t; }"
        : "=r"(a) : "l"(p));
    return a;
}

#define CP16(dst, src, sz) \
    asm volatile("cp.async.cg.shared.global [%0], [%1], 16, %2;" \
                 :: "r"(dst), "l"(src), "r"(sz))
#define CP_COMMIT() asm volatile("cp.async.commit_group;" ::: "memory")
#define CP_WAIT1()  asm volatile("cp.async.wait_group 1;" ::: "memory")
#define CP_WAIT0()  asm volatile("cp.async.wait_group 0;" ::: "memory")

__device__ __forceinline__ void ldx4(uint32_t* r, uint32_t addr) {
    asm volatile("ldmatrix.sync.aligned.m8n8.x4.shared.b16 {%0,%1,%2,%3}, [%4];"
                 : "=r"(r[0]), "=r"(r[1]), "=r"(r[2]), "=r"(r[3]) : "r"(addr));
}
__device__ __forceinline__ void ldx4t(uint32_t* r, uint32_t addr) {
    asm volatile("ldmatrix.sync.aligned.m8n8.x4.trans.shared.b16 {%0,%1,%2,%3}, [%4];"
                 : "=r"(r[0]), "=r"(r[1]), "=r"(r[2]), "=r"(r[3]) : "r"(addr));
}
__device__ __forceinline__ void mma16816(float* d, const uint32_t* a, const uint32_t* b) {
    asm volatile("mma.sync.aligned.m16n8k16.row.col.f32.bf16.bf16.f32 "
                 "{%0,%1,%2,%3}, {%4,%5,%6,%7}, {%8,%9}, {%0,%1,%2,%3};"
                 : "+f"(d[0]), "+f"(d[1]), "+f"(d[2]), "+f"(d[3])
                 : "r"(a[0]), "r"(a[1]), "r"(a[2]), "r"(a[3]), "r"(b[0]), "r"(b[1]));
}
__device__ __forceinline__ void exp8(uint4 u, float* f) {
    f[0] = __uint_as_float(u.x << 16); f[1] = __uint_as_float(u.x & 0xffff0000u);
    f[2] = __uint_as_float(u.y << 16); f[3] = __uint_as_float(u.y & 0xffff0000u);
    f[4] = __uint_as_float(u.z << 16); f[5] = __uint_as_float(u.z & 0xffff0000u);
    f[6] = __uint_as_float(u.w << 16); f[7] = __uint_as_float(u.w & 0xffff0000u);
}

#define SPIN_ON(ctr, target) do {                                             \
        if (threadIdx.x == 0) {                                               \
            while (atomicAdd(&(ctr), 0u) < (target)) { }                      \
            __threadfence();                                                  \
        }                                                                     \
        __syncthreads();                                                      \
    } while (0)

// ---------------------------------------------------------------------------
// GEMM tile config: BM=256, BN=128, BK=32, 512 threads (4x4 warps), 3-stage.
// ---------------------------------------------------------------------------
#define A_ROWB 80u
#define A_TILE (256u * A_ROWB)
#define B_ROWB 272u
#define B_TILE (32u * B_ROWB)
#define STAGE  (A_TILE + B_TILE)        // 29184
#define EP_ROWB 528u
#define GEMM_SMEM (3u * STAGE)          // 87552 > 128*EP_ROWB (67584)

#define GEMM_DECLS()                                                           \
    const uint32_t sb = smem_to_u32(sm);                                       \
    const int tid = threadIdx.x;                                               \
    const int wid = tid >> 5, lane = tid & 31;                                 \
    const int arow = tid >> 1;                                                 \
    const int c2   = (tid & 1) * 2;                                            \
    const uint32_t aOff = arow * A_ROWB + c2 * 16;                             \
    const int cloc = tid >> 4;                                                 \
    const int lcol = (tid & 15) * 8;                                           \
    const int r8 = lane & 7, sel = lane >> 3;                                  \
    const int warp_m = wid >> 2, warp_n = wid & 3;                             \
    const uint32_t aRel = (uint32_t)((warp_m * 64 + r8 + (sel & 1) * 8) * A_ROWB \
                                     + (sel >> 1) * 16);                       \
    const uint32_t bRel = (uint32_t)(A_TILE                                    \
                          + ((sel & 1) * 8 + r8) * B_ROWB                      \
                          + (warp_n * 32 + (sel >> 1) * 8) * 2)

#define ISSUE_A(kc, st) do {                                                  \
        const uint32_t base = sb + (uint32_t)(st) * STAGE;                    \
        const int ko = (kc) * 64;                                             \
        CP16(base + aOff,      srcAh + ko,      16u);                         \
        CP16(base + aOff + 16, srcAh + ko + 16, 16u);                         \
        CP_COMMIT();                                                          \
    } while (0)

#define STS_B2(st, vv) do {                                                   \
        char* bp = sm + (size_t)(st) * STAGE + A_TILE                         \
                   + (size_t)cloc * B_ROWB + lcol * 2;                        \
        uint4 p0;                                                             \
        __nv_bfloat162 t;                                                     \
        t = __float22bfloat162_rn(make_float2((vv)[0].x, (vv)[0].y)); p0.x = *(uint32_t*)&t; \
        t = __float22bfloat162_rn(make_float2((vv)[0].z, (vv)[0].w)); p0.y = *(uint32_t*)&t; \
        t = __float22bfloat162_rn(make_float2((vv)[1].x, (vv)[1].y)); p0.z = *(uint32_t*)&t; \
        t = __float22bfloat162_rn(make_float2((vv)[1].z, (vv)[1].w)); p0.w = *(uint32_t*)&t; \
        *(uint4*)(bp) = p0;                                                   \
    } while (0)

// 3-stage mainloop: B loaded 2 chunks ahead (double reg buffer),
// cp.async A at wait_group 1 depth. Same k-order as 2-stage (bit-identical).
#define GEMM_MAINLOOP(LDG_B_MACRO)                                            \
    float acc[4][4][4];                                                       \
    _Pragma("unroll")                                                         \
    for (int i = 0; i < 4; ++i)                                               \
        _Pragma("unroll")                                                     \
        for (int j = 0; j < 4; ++j)                                           \
            _Pragma("unroll")                                                 \
            for (int k = 0; k < 4; ++k) acc[i][j][k] = 0.f;                   \
    float4 vbuf[2][2];                                                        \
    LDG_B_MACRO(0, vbuf[0]);                                                  \
    LDG_B_MACRO(1, vbuf[1]);                                                  \
    ISSUE_A(0, 0);                                                            \
    ISSUE_A(1, 1);                                                            \
    STS_B2(0, vbuf[0]);                                                       \
    STS_B2(1, vbuf[1]);                                                       \
    LDG_B_MACRO(2, vbuf[0]);                                                  \
    CP_WAIT1();                                                               \
    __syncthreads();                                                          \
    for (int kc = 0; kc < 8; ++kc) {                                          \
        const int st = kc % 3;                                                \
        if (kc < 6) ISSUE_A(kc + 2, (kc + 2) % 3);                            \
        if (kc < 5) LDG_B_MACRO(kc + 3, vbuf[(kc + 1) & 1]);                  \
        const uint32_t stage = sb + (uint32_t)st * STAGE;                     \
        _Pragma("unroll")                                                     \
        for (int ks = 0; ks < 2; ++ks) {                                      \
            uint32_t bf[8];                                                   \
            ldx4t(bf,     stage + bRel + ks * 16 * B_ROWB);                   \
            ldx4t(bf + 4, stage + bRel + ks * 16 * B_ROWB + 32);              \
            uint32_t af[4];                                                   \
            _Pragma("unroll")                                                 \
            for (int mt = 0; mt < 4; ++mt) {                                  \
                ldx4(af, stage + aRel + ks * 32 + mt * 16 * A_ROWB);          \
                _Pragma("unroll")                                             \
                for (int nt = 0; nt < 4; ++nt)                                \
                    mma16816(acc[mt][nt], af, bf + (nt >> 1) * 4 + (nt & 1) * 2); \
            }                                                                 \
        }                                                                     \
        if (kc < 6) { STS_B2((kc + 2) % 3, vbuf[kc & 1]); CP_WAIT1(); }       \
        else if (kc == 6) CP_WAIT0();                                         \
        __syncthreads();                                                      \
    }

#define GEMM_STAGE_EP()                                                       \
    {                                                                         \
        float bv[4][2];                                                       \
        _Pragma("unroll")                                                     \
        for (int mt = 0; mt < 4; ++mt) {                                      \
            const int m = warp_m * 64 + mt * 16 + (lane >> 2);                \
            bv[mt][0] = bias[m];                                              \
            bv[mt][1] = bias[m + 8];                                          \
        }                                                                     \
        __nv_bfloat16* ep = (__nv_bfloat16*)sm;                               \
        _Pragma("unroll")                                                     \
        for (int mt = 0; mt < 4; ++mt) {                                      \
            const int m = warp_m * 64 + mt * 16 + (lane >> 2);                \
            _Pragma("unroll")                                                 \
            for (int nt = 0; nt < 4; ++nt) {                                  \
                const int n = warp_n * 32 + nt * 8 + (lane & 3) * 2;          \
                ep[(size_t)n       * 264 + m]     = __float2bfloat16(acc[mt][nt][0] + bv[mt][0]); \
                ep[(size_t)(n + 1) * 264 + m]     = __float2bfloat16(acc[mt][nt][1] + bv[mt][0]); \
                ep[(size_t)n       * 264 + m + 8] = __float2bfloat16(acc[mt][nt][2] + bv[mt][1]); \
                ep[(size_t)(n + 1) * 264 + m + 8] = __float2bfloat16(acc[mt][nt][3] + bv[mt][1]); \
            }                                                                 \
        }                                                                     \
        __syncthreads();                                                      \
    }

// ---------------------------------------------------------------------------
// Launch A: 148 blocks (one full wave — co-residency guaranteed).
//   0..3   : W->bf16 converters
//   4..147 : small gemms (scales 1..3), spin on converters
// ---------------------------------------------------------------------------
__global__ __launch_bounds__(512, 1)
void small_conv(const float* __restrict__ f1, const float* __restrict__ f2,
                const float* __restrict__ f3,
                const float* __restrict__ w0, const float* __restrict__ w1,
                const float* __restrict__ w2, const float* __restrict__ w3,
                const float* __restrict__ b1, const float* __restrict__ b2,
                const float* __restrict__ b3)
{
    extern __shared__ char sm[];
    const int id = blockIdx.x;

    if (id < 4) {
        const float* w = (id == 0) ? w0 : (id == 1) ? w1 : (id == 2) ? w2 : w3;
        for (int i = threadIdx.x; i < 16384; i += 512) {
            const float4 v = ((const float4*)w)[i];
            __nv_bfloat162 lo = __float22bfloat162_rn(make_float2(v.x, v.y));
            __nv_bfloat162 hi = __float22bfloat162_rn(make_float2(v.z, v.w));
            uint2 pk;
            pk.x = *(uint32_t*)&lo;
            pk.y = *(uint32_t*)&hi;
            ((uint2*)g_Wh[id])[i] = pk;
        }
        __syncthreads();
        if (threadIdx.x == 0) { __threadfence(); atomicAdd(&g_wdone, 1u); }
        return;
    }

    GEMM_DECLS();
    const int sid = id - 4;
    int s, off, L;
    const float* F;
    const float* bias;
    __nv_bfloat16* P;
    if (sid < 104)      { s = 1; off = 0;   L = 1600; F = f1; bias = b1; P = g_P1; }
    else if (sid < 136) { s = 2; off = 104; L = 400;  F = f2; bias = b2; P = g_P2; }
    else                { s = 3; off = 136; L = 100;  F = f3; bias = b3; P = g_P3; }
    const int local = sid - off;
    const int l0    = (local >> 3) * 128;
    const int batch = local & 7;

    const float* Fb = F + (size_t)batch * C256 * L;
    __nv_bfloat16* Pb = P + (size_t)batch * L * C256;
    const char* srcAh = (const char*)(g_Wh[s] + (size_t)arow * C256) + c2 * 16;

    SPIN_ON(g_wdone, 4u);

#define LDG_BS(kc, vv) do {                                                   \
        const int ch = (kc) * 32 + cloc;                                      \
        const float* rp = Fb + (size_t)ch * L + l0 + lcol;                    \
        _Pragma("unroll")                                                     \
        for (int i = 0; i < 2; ++i)                                           \
            (vv)[i] = (l0 + lcol + i * 4 < L) ? *(const float4*)(rp + i * 4)  \
                                              : make_float4(0.f, 0.f, 0.f, 0.f); \
    } while (0)

    GEMM_MAINLOOP(LDG_BS);
    GEMM_STAGE_EP();

    const int n = tid >> 2, quarter = tid & 3;
    if (l0 + n < L) {
        const uint4* src = (const uint4*)((const char*)sm + (size_t)n * EP_ROWB + quarter * 128);
        uint4* dst = (uint4*)(Pb + (size_t)(l0 + n) * C256 + quarter * 64);
#pragma unroll
        for (int i = 0; i < 8; ++i) dst[i] = src[i];
    }
#undef LDG_BS
}

// ---------------------------------------------------------------------------
// Launch B: 440 blocks.
//   0..39   : coarse pair sums (wave-1 riders)
//   40..439 : scale-0 gemm + fused fine cosine:
//             8-lane groups, 2 pixels/group, one batched 11-dot reduce
//   last ticket: final softmax + counter reset
// ---------------------------------------------------------------------------
__global__ __launch_bounds__(512, 1)
void gemm0_fused(const float* __restrict__ f0, const float* __restrict__ b0,
                 float* __restrict__ out)
{
    extern __shared__ char sm[];
    __shared__ float sh2[16][3];
    __shared__ unsigned int sh_last;
    const int id = blockIdx.x;

    if (id >= 40) {
        GEMM_DECLS();
        const int fid   = id - 40;           // 0..399
        const int l0    = (fid >> 3) * 128;
        const int batch = fid & 7;
        const float* Fb = f0 + (size_t)batch * C256 * 6400;
        const float* bias = b0;
        const char* srcAh = (const char*)(g_Wh[0] + (size_t)arow * C256) + c2 * 16;

#define LDG_B0(kc, vv) do {                                                   \
        const int ch = (kc) * 32 + cloc;                                      \
        const float* rp = Fb + (size_t)ch * 6400 + l0 + lcol;                 \
        (vv)[0] = *(const float4*)(rp);                                       \
        (vv)[1] = *(const float4*)(rp + 4);                                   \
    } while (0)

        GEMM_MAINLOOP(LDG_B0);
        GEMM_STAGE_EP();

        // ---- fine cosine: warp = 8 consecutive pixels (8-aligned, same row).
        //      8-lane group g handles pixels 2g, 2g+1 (same x1/x2/x3 indices).
        //      11 dot accumulators, ONE 3-round group reduce + 2-round merge. ----
        const int g   = lane >> 3;           // group 0..3
        const int q   = lane & 7;            // lane within group
        const int lb  = l0 + wid * 8;
        const int h   = lb / 80;
        const int w8  = lb - h * 80;         // multiple of 8

        const uint4* x1p = (const uint4*)(g_P1 + ((size_t)(batch * 1600 + (h >> 1) * 40 + (w8 >> 1)) + g) * C256);
        const uint4* x2p = (const uint4*)(g_P2 + ((size_t)(batch *  400 + (h >> 2) * 20 + (w8 >> 2)) + (g >> 1)) * C256);
        const uint4* x3p = (const uint4*)(g_P3 + (size_t)(batch * 100 + (h >> 3) * 10 + (w8 >> 3)) * C256);
        const char*  e0a = sm + (size_t)(wid * 8 + 2 * g)     * EP_ROWB;
        const char*  e0b = sm + (size_t)(wid * 8 + 2 * g + 1) * EP_ROWB;

        // d: 0=n0a 1=n0b 2=d1a 3=d1b 4=d2a 5=d2b 6=d3a 7=d3b 8=n1 9=n2 10=n3
        float d[11];
#pragma unroll
        for (int k = 0; k < 11; ++k) d[k] = 0.f;

#pragma unroll
        for (int j = 0; j < 4; ++j) {
            const int idx = q + 8 * j;
            float fa[8], fb[8], f1[8], f2[8], f3[8];
            exp8(*(const uint4*)(e0a + idx * 16), fa);
            exp8(*(const uint4*)(e0b + idx * 16), fb);
            exp8(x1p[idx], f1);
            exp8(x2p[idx], f2);
            exp8(x3p[idx], f3);
#pragma unroll
            for (int e = 0; e < 8; ++e) {
                d[0]  += fa[e] * fa[e];
                d[1]  += fb[e] * fb[e];
                d[2]  += fa[e] * f1[e];
                d[3]  += fb[e] * f1[e];
                d[4]  += fa[e] * f2[e];
                d[5]  += fb[e] * f2[e];
                d[6]  += fa[e] * f3[e];
                d[7]  += fb[e] * f3[e];
                d[8]  += f1[e] * f1[e];
                d[9]  += f2[e] * f2[e];
                d[10] += f3[e] * f3[e];
            }
        }
        // 3-round reduce within the 8-lane group
#pragma unroll
        for (int off = 4; off > 0; off >>= 1) {
#pragma unroll
            for (int k = 0; k < 11; ++k)
                d[k] += __shfl_xor_sync(0xFFFFFFFFu, d[k], off);
        }
        // per-group cosines (2 pixels)
        const float rn1 = rsqrtf(d[8]);
        const float rn2 = rsqrtf(d[9]);
        const float rn3 = rsqrtf(d[10]);
        const float r0a = rsqrtf(d[0]);
        const float r0b = rsqrtf(d[1]);
        float a01 = d[2] * r0a * rn1 + d[3] * r0b * rn1;
        float a02 = d[4] * r0a * rn2 + d[5] * r0b * rn2;
        float a03 = d[6] * r0a * rn3 + d[7] * r0b * rn3;
        // merge the 4 groups (valid on all lanes)
#pragma unroll
        for (int off = 8; off <= 16; off <<= 1) {
            a01 += __shfl_xor_sync(0xFFFFFFFFu, a01, off);
            a02 += __shfl_xor_sync(0xFFFFFFFFu, a02, off);
            a03 += __shfl_xor_sync(0xFFFFFFFFu, a03, off);
        }
        if (lane == 0) { sh2[wid][0] = a01; sh2[wid][1] = a02; sh2[wid][2] = a03; }
        __syncthreads();
        if (tid == 0) {
            float* dst = &g_part_fine[((size_t)batch * 50 + (fid >> 3)) * 3];
#pragma unroll
            for (int k = 0; k < 3; ++k) {
                float ss = 0.f;
#pragma unroll
                for (int i = 0; i < 16; ++i) ss += sh2[i][k];
                dst[k] = ss;
            }
        }
#undef LDG_B0
    } else {
        // ---- coarse pairs (P1..P3 ready via stream order) ----
        const int tid = threadIdx.x;
        const int wid = tid >> 5, lane = tid & 31;
        const int batch = id / 5;
        const int seg   = id - batch * 5;   // 0..4
        float a12 = 0.f, a13 = 0.f, a23 = 0.f;
        for (int i = 0; i < 20; ++i) {
            const int loc = seg * 320 + wid * 20 + i;
            const int h1 = loc / 40;
            const int w1 = loc - h1 * 40;
            const uint4 u1 = ((const uint4*)(g_P1 + (size_t)(batch * 1600 + loc) * C256))[lane];
            const uint4 u2 = ((const uint4*)(g_P2 + (size_t)(batch *  400 + (h1 >> 1) * 20 + (w1 >> 1)) * C256))[lane];
            const uint4 u3 = ((const uint4*)(g_P3 + (size_t)(batch *  100 + (h1 >> 2) * 10 + (w1 >> 2)) * C256))[lane];
            float e1[8], e2[8], e3[8];
            exp8(u1, e1); exp8(u2, e2); exp8(u3, e3);
            float d[6];
#pragma unroll
            for (int k = 0; k < 6; ++k) d[k] = 0.f;
#pragma unroll
            for (int e = 0; e < 8; ++e) {
                d[0] += e1[e] * e1[e];
                d[1] += e2[e] * e2[e];
                d[2] += e3[e] * e3[e];
                d[3] += e1[e] * e2[e];
                d[4] += e1[e] * e3[e];
                d[5] += e2[e] * e3[e];
            }
#pragma unroll
            for (int off = 16; off > 0; off >>= 1) {
#pragma unroll
                for (int k = 0; k < 6; ++k)
                    d[k] += __shfl_xor_sync(0xFFFFFFFFu, d[k], off);
            }
            if (lane == 0) {
                const float r1 = rsqrtf(d[0]);
                const float r2 = rsqrtf(d[1]);
                const float r3 = rsqrtf(d[2]);
                a12 += d[3] * r1 * r2;
                a13 += d[4] * r1 * r3;
                a23 += d[5] * r2 * r3;
            }
        }
        if (lane == 0) { sh2[wid][0] = a12 * 4.f; sh2[wid][1] = a13 * 4.f; sh2[wid][2] = a23 * 4.f; }
        __syncthreads();
        if (tid == 0) {
            float* dst = &g_part_coarse[((size_t)batch * 5 + seg) * 3];
#pragma unroll
            for (int k = 0; k < 3; ++k) {
                float ss = 0.f;
#pragma unroll
                for (int i = 0; i < 16; ++i) ss += sh2[i][k];
                dst[k] = ss;
            }
        }
    }

    // ---- ticket + final softmax ----
    __syncthreads();
    if (threadIdx.x == 0) {
        __threadfence();
        sh_last = (atomicAdd(&g_ticket, 1u) == 439u);
    }
    __syncthreads();
    if (sh_last) {
        __threadfence();
        const int t = threadIdx.x;
        if (t < 8) {
            float s6[6] = {0.f, 0.f, 0.f, 0.f, 0.f, 0.f};
            for (int i = 0; i < 50; ++i) {
#pragma unroll
                for (int k = 0; k < 3; ++k)
                    s6[k] += g_part_fine[((size_t)t * 50 + i) * 3 + k];
            }
            for (int i = 0; i < 5; ++i) {
#pragma unroll
                for (int k = 0; k < 3; ++k)
                    s6[3 + k] += g_part_coarse[((size_t)t * 5 + i) * 3 + k];
            }
            const float inv = 1.0f / 6400.0f;
            float a[4][4];
            a[0][0] = a[1][1] = a[2][2] = a[3][3] = 1.0f;
            a[0][1] = a[1][0] = s6[0] * inv;
            a[0][2] = a[2][0] = s6[1] * inv;
            a[0][3] = a[3][0] = s6[2] * inv;
            a[1][2] = a[2][1] = s6[3] * inv;
            a[1][3] = a[3][1] = s6[4] * inv;
            a[2][3] = a[3][2] = s6[5] * inv;
            for (int i = 0; i < 4; ++i) {
                float m = a[i][0];
                for (int j = 1; j < 4; ++j) m = fmaxf(m, a[i][j]);
                float e[4], sum = 0.f;
                for (int j = 0; j < 4; ++j) { e[j] = expf(a[i][j] - m); sum += e[j]; }
                for (int j = 0; j < 4; ++j) out[t * 16 + i * 4 + j] = e[j] / sum;
            }
        }
        if (t == 0) {            // reset for next graph replay
            g_ticket = 0;
            g_wdone = 0;
        }
    }
}

// ---------------------------------------------------------------------------
extern "C" void kernel_launch(void* const* d_in, const int* in_sizes, int n_in,
                              void* d_out, int out_size)
{
    const float* f[4]  = {nullptr, nullptr, nullptr, nullptr};
    const float* w[4]  = {nullptr, nullptr, nullptr, nullptr};
    const float* bs[4] = {nullptr, nullptr, nullptr, nullptr};
    int wi = 0, bi = 0;
    for (int i = 0; i < n_in; ++i) {
        long sz = in_sizes[i];
        const float* p = (const float*)d_in[i];
        if      (sz == 65536)    { if (wi < 4) w[wi++]  = p; }
        else if (sz == 256)      { if (bi < 4) bs[bi++] = p; }
        else if (sz == 13107200) f[0] = p;   // 8*256*6400
        else if (sz == 3276800)  f[1] = p;   // 8*256*1600
        else if (sz == 819200)   f[2] = p;   // 8*256*400
        else if (sz == 204800)   f[3] = p;   // 8*256*100
    }

    cudaFuncSetAttribute(small_conv,  cudaFuncAttributeMaxDynamicSharedMemorySize, GEMM_SMEM);
    cudaFuncSetAttribute(gemm0_fused, cudaFuncAttributeMaxDynamicSharedMemorySize, GEMM_SMEM);

    small_conv<<<148, 512, GEMM_SMEM>>>(f[1], f[2], f[3],
                                        w[0], w[1], w[2], w[3],
                                        bs[1], bs[2], bs[3]);
    gemm0_fused<<<440, 512, GEMM_SMEM>>>(f[0], bs[0], (float*)d_out);
}